// round 2
// baseline (speedup 1.0000x reference)
#include <cuda_runtime.h>
#include <cstddef>

// ---------------------------------------------------------------------------
// GMM (MoNet) graph conv, 2 layers, each computed as:
//   z[n,k,:] = sum_{e in edges(n)} gauss[e,k] * x[col[e],:]     (gather phase)
//   out[n,h] = sum_k sum_f z[n,k,f] * W[k,f,h]                  (tiny GEMM)
// Layer1: F=64 -> H=32 (to scratch), Layer2: F=32 -> H=16 (to d_out)
// NOTE: row_ptr/col_idx are int32 on device (JAX x64 disabled).
// ---------------------------------------------------------------------------

#define MAXN 131072
__device__ float g_hidden[MAXN * 32];   // layer-1 output scratch

static constexpr int KNUM = 3;

template<int F, int H, int GROUP, int NWARP>
static constexpr int smem_floats() {
    // Wt[K][H][F+4] + zs[NWARP][GROUP][K][F] + ms[16]
    return KNUM * H * (F + 4) + NWARP * GROUP * KNUM * F + 16;
}

template<int F, int H, int GROUP, int NWARP>
__global__ void __launch_bounds__(NWARP * 32)
gmm_layer(const int* __restrict__ row_ptr,
          const int* __restrict__ col_idx,
          const float* __restrict__ p,        // [E,2]
          const float* __restrict__ mu,       // [3,2]
          const float* __restrict__ sigma,    // [3,2]
          const float* __restrict__ W,        // [3,F,H] row-major
          const float* __restrict__ x_in,     // [N,F]  (null => g_hidden)
          float* __restrict__ out_p,          // [N,H]  (null => g_hidden)
          int n_nodes)
{
    constexpr int K  = KNUM;
    constexpr int VF = F / 32;       // floats per lane in gather (2 or 1)
    constexpr int FP = F + 4;        // padded W row to kill bank conflicts

    extern __shared__ float smem[];
    float (*Wt)[H][FP] = (float (*)[H][FP])smem;                       // transposed W
    float (*zs)[GROUP][K][F] = (float (*)[GROUP][K][F])(smem + K * H * FP);
    float* ms = smem + K * H * FP + NWARP * GROUP * K * F;             // mu(6) + invvar(6)

    const float* __restrict__ x  = x_in  ? x_in  : g_hidden;
    float* __restrict__ out      = out_p ? out_p : g_hidden;

    const int tid  = threadIdx.x;
    const int lane = tid & 31;
    const int wid  = tid >> 5;

    // Stage W transposed: Wt[k][h][f] = W[k*F*H + f*H + h]
    for (int i = tid; i < K * F * H; i += NWARP * 32) {
        int k = i / (F * H);
        int f = (i / H) % F;
        int h = i % H;
        Wt[k][h][f] = W[i];
    }
    if (tid < 6) {
        ms[tid] = mu[tid];
        float s = sigma[tid];
        ms[6 + tid] = 1.0f / (s * s);
    }
    __syncthreads();

    const int gwarp  = blockIdx.x * NWARP + wid;
    const int nwarps = gridDim.x * NWARP;

    for (int base = gwarp * GROUP; base < n_nodes; base += nwarps * GROUP) {
        const int ng = min(GROUP, n_nodes - base);

        // ---------------- gather / aggregate phase ----------------
        for (int g = 0; g < ng; g++) {
            const int n = base + g;
            const int start = row_ptr[n];
            const int deg   = row_ptr[n + 1] - start;

            float acc[K][VF];
            #pragma unroll
            for (int k = 0; k < K; k++)
                #pragma unroll
                for (int v = 0; v < VF; v++) acc[k][v] = 0.0f;

            for (int j0 = 0; j0 < deg; j0 += 32) {
                const int j   = j0 + lane;
                const int cnt = min(32, deg - j0);
                int   c = 0;
                float g0 = 0.0f, g1 = 0.0f, g2 = 0.0f;
                if (j < deg) {
                    const int e = start + j;
                    c = col_idx[e];
                    const float2 pv = __ldg((const float2*)p + e);
                    float dx, dy, s;
                    dx = pv.x - ms[0]; dy = pv.y - ms[1];
                    s  = dx * dx * ms[6]  + dy * dy * ms[7];
                    g0 = __expf(-0.5f * s);
                    dx = pv.x - ms[2]; dy = pv.y - ms[3];
                    s  = dx * dx * ms[8]  + dy * dy * ms[9];
                    g1 = __expf(-0.5f * s);
                    dx = pv.x - ms[4]; dy = pv.y - ms[5];
                    s  = dx * dx * ms[10] + dy * dy * ms[11];
                    g2 = __expf(-0.5f * s);
                }

                #define GMM_BODY(JJ) do {                                          \
                    const int   cc = __shfl_sync(0xffffffffu, c,  (JJ));           \
                    const float w0 = __shfl_sync(0xffffffffu, g0, (JJ));           \
                    const float w1 = __shfl_sync(0xffffffffu, g1, (JJ));           \
                    const float w2 = __shfl_sync(0xffffffffu, g2, (JJ));           \
                    const float* xr = x + (size_t)cc * F;                          \
                    if constexpr (VF == 2) {                                       \
                        const float2 xv = __ldg((const float2*)xr + lane);         \
                        acc[0][0] = fmaf(w0, xv.x, acc[0][0]);                     \
                        acc[0][1] = fmaf(w0, xv.y, acc[0][1]);                     \
                        acc[1][0] = fmaf(w1, xv.x, acc[1][0]);                     \
                        acc[1][1] = fmaf(w1, xv.y, acc[1][1]);                     \
                        acc[2][0] = fmaf(w2, xv.x, acc[2][0]);                     \
                        acc[2][1] = fmaf(w2, xv.y, acc[2][1]);                     \
                    } else {                                                       \
                        const float xv = __ldg(xr + lane);                         \
                        acc[0][0] = fmaf(w0, xv, acc[0][0]);                       \
                        acc[1][0] = fmaf(w1, xv, acc[1][0]);                       \
                        acc[2][0] = fmaf(w2, xv, acc[2][0]);                       \
                    }                                                              \
                } while (0)

                if (cnt == 16) {
                    #pragma unroll
                    for (int jj = 0; jj < 16; jj++) GMM_BODY(jj);
                } else if (cnt == 32) {
                    #pragma unroll
                    for (int jj = 0; jj < 32; jj++) GMM_BODY(jj);
                } else {
                    for (int jj = 0; jj < cnt; jj++) GMM_BODY(jj);
                }
                #undef GMM_BODY
            }

            // park z in shared for the GEMM phase
            #pragma unroll
            for (int k = 0; k < K; k++)
                #pragma unroll
                for (int v = 0; v < VF; v++)
                    zs[wid][g][k][lane * VF + v] = acc[k][v];
        }
        __syncwarp();

        // ---------------- per-node GEMM phase ----------------
        // H==32: lane == h. H==16: lanes split F range in half, shfl-reduce.
        constexpr int PARTS = 32 / H;
        constexpr int FH    = F / PARTS;
        const int hl = lane % H;
        const int f0 = (PARTS == 2) ? (lane / H) * FH : 0;

        float og[GROUP];
        #pragma unroll
        for (int g = 0; g < GROUP; g++) og[g] = 0.0f;

        #pragma unroll
        for (int k = 0; k < K; k++) {
            #pragma unroll
            for (int f = 0; f < FH; f += 4) {
                const float4 wv = *(const float4*)&Wt[k][hl][f0 + f];
                #pragma unroll
                for (int g = 0; g < GROUP; g++) {
                    const float4 zv = *(const float4*)&zs[wid][g][k][f0 + f];
                    og[g] = fmaf(wv.x, zv.x, og[g]);
                    og[g] = fmaf(wv.y, zv.y, og[g]);
                    og[g] = fmaf(wv.z, zv.z, og[g]);
                    og[g] = fmaf(wv.w, zv.w, og[g]);
                }
            }
        }
        if constexpr (PARTS == 2) {
            #pragma unroll
            for (int g = 0; g < GROUP; g++)
                og[g] += __shfl_down_sync(0xffffffffu, og[g], H);
        }
        for (int g = 0; g < ng; g++) {
            if (lane < H)
                out[(size_t)(base + g) * H + lane] = og[g];
        }
        __syncwarp();
    }
}

extern "C" void kernel_launch(void* const* d_in, const int* in_sizes, int n_in,
                              void* d_out, int out_size)
{
    const int*   row_ptr = (const int*)d_in[0];     // int32 (JAX x64 disabled)
    const int*   col_idx = (const int*)d_in[1];     // int32
    const float* x       = (const float*)d_in[2];
    const float* p       = (const float*)d_in[3];
    const float* mu      = (const float*)d_in[4];
    const float* sg      = (const float*)d_in[5];
    const float* W1      = (const float*)d_in[6];
    const float* W2      = (const float*)d_in[7];

    const int n_nodes = in_sizes[0] - 1;

    constexpr int NWARP = 8;
    constexpr int GROUP = 4;
    constexpr int TPB   = NWARP * 32;

    const int blocks = (n_nodes + GROUP * NWARP - 1) / (GROUP * NWARP);

    constexpr size_t smem1 = (size_t)smem_floats<64, 32, GROUP, NWARP>() * sizeof(float);
    constexpr size_t smem2 = (size_t)smem_floats<32, 16, GROUP, NWARP>() * sizeof(float);

    cudaFuncSetAttribute(gmm_layer<64, 32, GROUP, NWARP>,
                         cudaFuncAttributeMaxDynamicSharedMemorySize, (int)smem1);
    cudaFuncSetAttribute(gmm_layer<32, 16, GROUP, NWARP>,
                         cudaFuncAttributeMaxDynamicSharedMemorySize, (int)smem2);

    // Layer 1: input_feature -> g_hidden
    gmm_layer<64, 32, GROUP, NWARP><<<blocks, TPB, smem1>>>(
        row_ptr, col_idx, p, mu, sg, W1, x, nullptr, n_nodes);

    // Layer 2: g_hidden -> d_out
    gmm_layer<32, 16, GROUP, NWARP><<<blocks, TPB, smem2>>>(
        row_ptr, col_idx, p, mu, sg, W2, nullptr, (float*)d_out, n_nodes);
}

// round 3
// speedup vs baseline: 1.0959x; 1.0959x over previous
#include <cuda_runtime.h>
#include <cstddef>

// ---------------------------------------------------------------------------
// GMM (MoNet) graph conv, 2 layers:
//   z[n,k,:] = sum_{e in edges(n)} gauss[e,k] * x[col[e],:]     (gather)
//   out[n,h] = sum_k sum_f z[n,k,f] * W[k,f,h]                  (tiny GEMM)
// Layer1: F=64 -> H=32 (scratch), Layer2: F=32 -> H=16 (d_out)
// row_ptr/col_idx are int32. Edge gaussians staged in smem (no shuffles).
// GEMM uses packed fma.rn.f32x2 on b64 register pairs.
// ---------------------------------------------------------------------------

#define MAXN 131072
__device__ float g_hidden[MAXN * 32];

typedef unsigned long long ull;

__device__ __forceinline__ ull pk2(float x, float y) {
    ull r; asm("mov.b64 %0, {%1,%2};" : "=l"(r) : "f"(x), "f"(y)); return r;
}
__device__ __forceinline__ void upk2(ull v, float& x, float& y) {
    asm("mov.b64 {%0,%1}, %2;" : "=f"(x), "=f"(y) : "l"(v));
}
__device__ __forceinline__ void ffma2(ull& d, ull a, ull b) {
    asm("fma.rn.f32x2 %0, %1, %2, %0;" : "+l"(d) : "l"(a), "l"(b));
}

static constexpr int KNUM = 3;

template<int F, int H, int GROUP, int NWARP>
static constexpr size_t smem_bytes() {
    // Wt[K][H][F+4] + zs[NWARP][GROUP][K][F] + ms[16]  (floats)  + stg float4
    return (size_t)(KNUM * H * (F + 4) + NWARP * GROUP * KNUM * F + 16) * 4
         + (size_t)NWARP * (GROUP * 16) * 16;
}

template<int F, int H, int GROUP, int NWARP>
__global__ void __launch_bounds__(NWARP * 32)
gmm_layer(const int* __restrict__ row_ptr,
          const int* __restrict__ col_idx,
          const float* __restrict__ p,        // [E,2]
          const float* __restrict__ mu,       // [3,2]
          const float* __restrict__ sigma,    // [3,2]
          const float* __restrict__ W,        // [3,F,H] row-major
          const float* __restrict__ x_in,     // [N,F]  (null => g_hidden)
          float* __restrict__ out_p,          // [N,H]  (null => g_hidden)
          int n_nodes)
{
    constexpr int K   = KNUM;
    constexpr int VF  = F / 32;          // 2 (layer1) or 1 (layer2)
    constexpr int FP  = F + 4;           // padded W rows (bank-conflict-free)
    constexpr int CAP = GROUP * 16;      // staged edges per warp

    extern __shared__ float smem[];
    float (*Wt)[H][FP] = (float (*)[H][FP])smem;
    float* zs_base = smem + K * H * FP;                       // [NWARP][GROUP][K][F]
    float4* stg    = (float4*)(zs_base + NWARP * GROUP * K * F);
    float* ms      = (float*)(stg + NWARP * CAP);             // mu(6) + invvar(6)

    const float* __restrict__ x = x_in  ? x_in  : g_hidden;
    float* __restrict__ out     = out_p ? out_p : g_hidden;

    const int tid  = threadIdx.x;
    const int lane = tid & 31;
    const int wid  = tid >> 5;

    // Stage W transposed: Wt[k][h][f] = W[k*F*H + f*H + h]
    for (int i = tid; i < K * F * H; i += NWARP * 32) {
        int k = i / (F * H);
        int f = (i / H) % F;
        int h = i % H;
        Wt[k][h][f] = W[i];
    }
    if (tid < 6) {
        ms[tid] = mu[tid];
        float s = sigma[tid];
        ms[6 + tid] = 1.0f / (s * s);
    }
    __syncthreads();

    // gaussian params in registers
    const float m0 = ms[0], m1 = ms[1], m2 = ms[2], m3 = ms[3], m4 = ms[4], m5 = ms[5];
    const float i0 = ms[6], i1 = ms[7], i2 = ms[8], i3 = ms[9], i4 = ms[10], i5 = ms[11];

    const int gwarp  = blockIdx.x * NWARP + wid;
    const int nwarps = gridDim.x * NWARP;
    float4* mystg = stg + wid * CAP;

    for (int base = gwarp * GROUP; base < n_nodes; base += nwarps * GROUP) {
        const int ng = min(GROUP, n_nodes - base);
        const int e0   = row_ptr[base];
        const int ecnt = row_ptr[base + ng] - e0;
        const bool fast = (ecnt <= CAP);

        // ---------- stage edge descriptors (g0,g1,g2,col) ----------
        if (fast) {
            for (int j = lane; j < ecnt; j += 32) {
                const int e  = e0 + j;
                const int cc = col_idx[e];
                const float2 pv = __ldg((const float2*)p + e);
                float dx, dy, s, g0, g1, g2;
                dx = pv.x - m0; dy = pv.y - m1; s = dx*dx*i0 + dy*dy*i1; g0 = __expf(-0.5f*s);
                dx = pv.x - m2; dy = pv.y - m3; s = dx*dx*i2 + dy*dy*i3; g1 = __expf(-0.5f*s);
                dx = pv.x - m4; dy = pv.y - m5; s = dx*dx*i4 + dy*dy*i5; g2 = __expf(-0.5f*s);
                mystg[j] = make_float4(g0, g1, g2, __int_as_float(cc));
            }
        }
        __syncwarp();

        // ---------- gather / aggregate ----------
        for (int g = 0; g < ng; g++) {
            const int n   = base + g;
            const int st  = row_ptr[n];
            const int deg = row_ptr[n + 1] - st;
            const int off = st - e0;

            if constexpr (VF == 2) {
                ull a0 = 0ull, a1 = 0ull, a2 = 0ull;
                if (fast) {
                    #define B1(J) do {                                                        \
                        const float4 ed = mystg[off + (J)];                                   \
                        const int cc = __float_as_int(ed.w);                                  \
                        const ull xv = __double_as_longlong(                                  \
                            __ldg((const double*)x + (size_t)cc * (F/2) + lane));             \
                        ffma2(a0, pk2(ed.x, ed.x), xv);                                       \
                        ffma2(a1, pk2(ed.y, ed.y), xv);                                       \
                        ffma2(a2, pk2(ed.z, ed.z), xv);                                       \
                    } while (0)
                    if (deg == 16) {
                        #pragma unroll
                        for (int j = 0; j < 16; j++) B1(j);
                    } else {
                        for (int j = 0; j < deg; j++) B1(j);
                    }
                    #undef B1
                } else {
                    // slow fallback: uniform loads, redundant gauss in all lanes
                    for (int j = 0; j < deg; j++) {
                        const int e  = st + j;
                        const int cc = __ldg(col_idx + e);
                        const float2 pv = __ldg((const float2*)p + e);
                        float dx, dy, s, g0, g1, g2;
                        dx = pv.x - m0; dy = pv.y - m1; s = dx*dx*i0 + dy*dy*i1; g0 = __expf(-0.5f*s);
                        dx = pv.x - m2; dy = pv.y - m3; s = dx*dx*i2 + dy*dy*i3; g1 = __expf(-0.5f*s);
                        dx = pv.x - m4; dy = pv.y - m5; s = dx*dx*i4 + dy*dy*i5; g2 = __expf(-0.5f*s);
                        const ull xv = __double_as_longlong(
                            __ldg((const double*)x + (size_t)cc * (F/2) + lane));
                        ffma2(a0, pk2(g0, g0), xv);
                        ffma2(a1, pk2(g1, g1), xv);
                        ffma2(a2, pk2(g2, g2), xv);
                    }
                }
                double* zd = (double*)(zs_base + (size_t)((wid * GROUP + g) * K) * F);
                zd[lane]             = __longlong_as_double(a0);
                zd[(F/2)   + lane]   = __longlong_as_double(a1);
                zd[(F/2)*2 + lane]   = __longlong_as_double(a2);
            } else {
                float a0 = 0.f, a1 = 0.f, a2 = 0.f;
                if (fast) {
                    #define B2(J) do {                                                        \
                        const float4 ed = mystg[off + (J)];                                   \
                        const int cc = __float_as_int(ed.w);                                  \
                        const float xv = __ldg(x + (size_t)cc * F + lane);                    \
                        a0 = fmaf(ed.x, xv, a0);                                              \
                        a1 = fmaf(ed.y, xv, a1);                                              \
                        a2 = fmaf(ed.z, xv, a2);                                              \
                    } while (0)
                    if (deg == 16) {
                        #pragma unroll
                        for (int j = 0; j < 16; j++) B2(j);
                    } else {
                        for (int j = 0; j < deg; j++) B2(j);
                    }
                    #undef B2
                } else {
                    for (int j = 0; j < deg; j++) {
                        const int e  = st + j;
                        const int cc = __ldg(col_idx + e);
                        const float2 pv = __ldg((const float2*)p + e);
                        float dx, dy, s, g0, g1, g2;
                        dx = pv.x - m0; dy = pv.y - m1; s = dx*dx*i0 + dy*dy*i1; g0 = __expf(-0.5f*s);
                        dx = pv.x - m2; dy = pv.y - m3; s = dx*dx*i2 + dy*dy*i3; g1 = __expf(-0.5f*s);
                        dx = pv.x - m4; dy = pv.y - m5; s = dx*dx*i4 + dy*dy*i5; g2 = __expf(-0.5f*s);
                        const float xv = __ldg(x + (size_t)cc * F + lane);
                        a0 = fmaf(g0, xv, a0);
                        a1 = fmaf(g1, xv, a1);
                        a2 = fmaf(g2, xv, a2);
                    }
                }
                float* zr = zs_base + (size_t)((wid * GROUP + g) * K) * F;
                zr[lane]         = a0;
                zr[F + lane]     = a1;
                zr[2 * F + lane] = a2;
            }
        }
        __syncwarp();

        // ---------- per-node GEMM: out[h] = sum_{k,f} z[k,f] * Wt[k][h][f] ----------
        constexpr int PARTS = 32 / H;    // 1 (layer1) or 2 (layer2)
        constexpr int FH    = F / PARTS;
        const int hl = lane % H;
        const int f0 = (PARTS == 2) ? (lane / H) * FH : 0;

        ull og2[GROUP];
        #pragma unroll
        for (int g = 0; g < GROUP; g++) og2[g] = 0ull;

        #pragma unroll
        for (int k = 0; k < K; k++) {
            const float* wrow = &Wt[k][hl][f0];
            #pragma unroll
            for (int f = 0; f < FH; f += 4) {
                const double2 wv = *(const double2*)(wrow + f);
                const ull wa = __double_as_longlong(wv.x);
                const ull wb = __double_as_longlong(wv.y);
                #pragma unroll
                for (int g = 0; g < GROUP; g++) {
                    const double2 zv = *(const double2*)
                        (zs_base + (size_t)((wid * GROUP + g) * K + k) * F + f0 + f);
                    ffma2(og2[g], wa, __double_as_longlong(zv.x));
                    ffma2(og2[g], wb, __double_as_longlong(zv.y));
                }
            }
        }

        float og[GROUP];
        #pragma unroll
        for (int g = 0; g < GROUP; g++) {
            float a, b; upk2(og2[g], a, b);
            og[g] = a + b;
        }
        if constexpr (PARTS == 2) {
            #pragma unroll
            for (int g = 0; g < GROUP; g++)
                og[g] += __shfl_down_sync(0xffffffffu, og[g], H);
        }
        for (int g = 0; g < ng; g++) {
            if (lane < H)
                out[(size_t)(base + g) * H + lane] = og[g];
        }
        __syncwarp();
    }
}

extern "C" void kernel_launch(void* const* d_in, const int* in_sizes, int n_in,
                              void* d_out, int out_size)
{
    const int*   row_ptr = (const int*)d_in[0];
    const int*   col_idx = (const int*)d_in[1];
    const float* x       = (const float*)d_in[2];
    const float* p       = (const float*)d_in[3];
    const float* mu      = (const float*)d_in[4];
    const float* sg      = (const float*)d_in[5];
    const float* W1      = (const float*)d_in[6];
    const float* W2      = (const float*)d_in[7];

    const int n_nodes = in_sizes[0] - 1;

    constexpr int NWARP = 8;
    constexpr int GROUP = 8;
    constexpr int TPB   = NWARP * 32;

    const int blocks = (n_nodes + GROUP * NWARP - 1) / (GROUP * NWARP);

    constexpr size_t smem1 = smem_bytes<64, 32, GROUP, NWARP>();
    constexpr size_t smem2 = smem_bytes<32, 16, GROUP, NWARP>();

    cudaFuncSetAttribute(gmm_layer<64, 32, GROUP, NWARP>,
                         cudaFuncAttributeMaxDynamicSharedMemorySize, (int)smem1);
    cudaFuncSetAttribute(gmm_layer<32, 16, GROUP, NWARP>,
                         cudaFuncAttributeMaxDynamicSharedMemorySize, (int)smem2);

    gmm_layer<64, 32, GROUP, NWARP><<<blocks, TPB, smem1>>>(
        row_ptr, col_idx, p, mu, sg, W1, x, nullptr, n_nodes);

    gmm_layer<32, 16, GROUP, NWARP><<<blocks, TPB, smem2>>>(
        row_ptr, col_idx, p, mu, sg, W2, nullptr, (float*)d_out, n_nodes);
}

// round 4
// speedup vs baseline: 1.2113x; 1.1053x over previous
#include <cuda_runtime.h>
#include <cstddef>

// ---------------------------------------------------------------------------
// GMM (MoNet) graph conv, 2 layers, restructured as transform-then-gather:
//   T: y[m, k*H+h] = sum_f x[m,f] * W[k,f,h]      (dense tiled ffma2 GEMM)
//   G: out[n,h]    = sum_e sum_k gauss[e,k] * y[col_e, k*H+h]   (flat gather)
// T1(64->96), G1(H=32), T2(32->48), G2(H=16).
// ---------------------------------------------------------------------------

#define MAXN 131072
__device__ float g_y1[MAXN * 96];   // xW1      [N,3,32]
__device__ float g_h [MAXN * 32];   // layer1 out
__device__ float g_y2[MAXN * 48];   // hW2      [N,3,16]

typedef unsigned long long ull;

__device__ __forceinline__ ull pk2(float x, float y) {
    ull r; asm("mov.b64 %0, {%1,%2};" : "=l"(r) : "f"(x), "f"(y)); return r;
}
__device__ __forceinline__ void upk2(ull v, float& x, float& y) {
    asm("mov.b64 {%0,%1}, %2;" : "=f"(x), "=f"(y) : "l"(v));
}
__device__ __forceinline__ void ffma2(ull& d, ull a, ull b) {
    asm("fma.rn.f32x2 %0, %1, %2, %0;" : "+l"(d) : "l"(a), "l"(b));
}

// ======================= transform (tiled GEMM) ============================
// Y[m, n] = sum_f X[m, f] * W[k, f, h],  n = k*H + h,  NCOL = 3*H
// blockDim 192 = 12 (n-dir) x 16 (m-dir); M-tile 128; per-thread 8m x NTILE n.
template<int KD, int NCOL, int H>
__global__ void __launch_bounds__(192)
transform_kernel(const float* __restrict__ X, const float* __restrict__ W,
                 float* __restrict__ Y, int n_nodes)
{
    constexpr int MT = 128;
    constexpr int XSTR = MT + 2;           // pad 2: conflict-free, 8B-aligned pairs
    constexpr int NTILE = NCOL / 12;       // 8 (T1) or 4 (T2)

    extern __shared__ float smem[];
    float* Xs = smem;                      // [KD][XSTR]
    float* Ws = smem + KD * XSTR;          // [KD][NCOL]

    const int tid = threadIdx.x;
    const int mt0 = blockIdx.x * MT;

    for (int i = tid; i < KD * NCOL; i += 192) {
        int f = i / NCOL, n = i % NCOL;
        int k = n / H, h = n % H;
        Ws[f * NCOL + n] = W[((size_t)k * KD + f) * H + h];
    }
    for (int i = tid; i < MT * KD; i += 192) {
        int m = i / KD, f = i % KD;
        float v = 0.f;
        if (mt0 + m < n_nodes) v = X[(size_t)(mt0 + m) * KD + f];
        Xs[f * XSTR + m] = v;
    }
    __syncthreads();

    const int tx = tid % 12;
    const int ty = tid / 12;               // 0..15
    const int m0 = ty * 8;

    ull acc[4][NTILE];
    #pragma unroll
    for (int i = 0; i < 4; i++)
        #pragma unroll
        for (int s = 0; s < NTILE; s++) acc[i][s] = 0ull;

    for (int f = 0; f < KD; f++) {
        ull a[4];
        #pragma unroll
        for (int i = 0; i < 4; i++)
            a[i] = *(const ull*)&Xs[f * XSTR + m0 + 2 * i];   // (x_m, x_m+1)
        #pragma unroll
        for (int s = 0; s < NTILE; s++) {
            const float w = Ws[f * NCOL + tx + 12 * s];
            const ull wb = pk2(w, w);
            #pragma unroll
            for (int i = 0; i < 4; i++) ffma2(acc[i][s], a[i], wb);
        }
    }

    #pragma unroll
    for (int i = 0; i < 4; i++) {
        const int m = mt0 + m0 + 2 * i;
        #pragma unroll
        for (int s = 0; s < NTILE; s++) {
            float v0, v1; upk2(acc[i][s], v0, v1);
            const int n = tx + 12 * s;
            if (m < n_nodes)     Y[(size_t)m * NCOL + n]       = v0;
            if (m + 1 < n_nodes) Y[(size_t)(m + 1) * NCOL + n] = v1;
        }
    }
}

// ========================= gather kernels ==================================
#define LOAD_GAUSS_PARAMS()                                                   \
    const float m0_ = mu[0], m1_ = mu[1], m2_ = mu[2],                        \
                m3_ = mu[3], m4_ = mu[4], m5_ = mu[5];                        \
    float s_;                                                                 \
    s_ = sigma[0]; const float i0_ = 1.f/(s_*s_);                             \
    s_ = sigma[1]; const float i1_ = 1.f/(s_*s_);                             \
    s_ = sigma[2]; const float i2_ = 1.f/(s_*s_);                             \
    s_ = sigma[3]; const float i3_ = 1.f/(s_*s_);                             \
    s_ = sigma[4]; const float i4_ = 1.f/(s_*s_);                             \
    s_ = sigma[5]; const float i5_ = 1.f/(s_*s_);

#define GAUSS3(pv, g0, g1, g2) do {                                           \
    float dx_, dy_, q_;                                                       \
    dx_ = (pv).x - m0_; dy_ = (pv).y - m1_;                                   \
    q_ = dx_*dx_*i0_ + dy_*dy_*i1_; g0 = __expf(-0.5f * q_);                  \
    dx_ = (pv).x - m2_; dy_ = (pv).y - m3_;                                   \
    q_ = dx_*dx_*i2_ + dy_*dy_*i3_; g1 = __expf(-0.5f * q_);                  \
    dx_ = (pv).x - m4_; dy_ = (pv).y - m5_;                                   \
    q_ = dx_*dx_*i4_ + dy_*dy_*i5_; g2 = __expf(-0.5f * q_);                  \
} while (0)

// ---- H = 32: one node per warp, 4 nodes per warp per block pass -----------
template<int NWARP>
__global__ void __launch_bounds__(NWARP * 32)
gather_h32(const int* __restrict__ row_ptr, const int* __restrict__ col_idx,
           const float2* __restrict__ p,
           const float* __restrict__ mu, const float* __restrict__ sigma,
           const float* __restrict__ y,      // [N, 96]
           float* __restrict__ out,          // [N, 32]
           int n_nodes)
{
    constexpr int GRP = 4, CAP = 64;
    __shared__ float4 stg[NWARP][CAP];

    const int lane = threadIdx.x & 31;
    const int wid  = threadIdx.x >> 5;
    const int base = (blockIdx.x * NWARP + wid) * GRP;
    if (base >= n_nodes) return;

    LOAD_GAUSS_PARAMS();

    const int ng   = min(GRP, n_nodes - base);
    const int e0   = row_ptr[base];
    const int ecnt = row_ptr[base + ng] - e0;
    const bool fast = (ecnt <= CAP);

    if (fast) {
        for (int j = lane; j < ecnt; j += 32) {
            const int e = e0 + j;
            const int c = col_idx[e];
            const float2 pv = __ldg(p + e);
            float g0, g1, g2; GAUSS3(pv, g0, g1, g2);
            stg[wid][j] = make_float4(g0, g1, g2, __int_as_float(c));
        }
    }
    __syncwarp();

    for (int g = 0; g < ng; g++) {
        const int n   = base + g;
        const int st  = row_ptr[n];
        const int deg = row_ptr[n + 1] - st;
        float a0 = 0.f, a1 = 0.f, a2 = 0.f;

        if (fast) {
            const float4* sd = &stg[wid][st - e0];
            #define G32_BODY(J) do {                                          \
                const float4 ed = sd[(J)];                                    \
                const int c = __float_as_int(ed.w);                           \
                const float* yr = y + (size_t)c * 96 + lane;                  \
                a0 = fmaf(ed.x, __ldg(yr),      a0);                          \
                a1 = fmaf(ed.y, __ldg(yr + 32), a1);                          \
                a2 = fmaf(ed.z, __ldg(yr + 64), a2);                          \
            } while (0)
            if (deg == 16) {
                #pragma unroll
                for (int j = 0; j < 16; j++) G32_BODY(j);
            } else {
                for (int j = 0; j < deg; j++) G32_BODY(j);
            }
            #undef G32_BODY
        } else {
            for (int j = 0; j < deg; j++) {
                const int e = st + j;
                const int c = __ldg(col_idx + e);
                const float2 pv = __ldg(p + e);
                float g0, g1, g2; GAUSS3(pv, g0, g1, g2);
                const float* yr = y + (size_t)c * 96 + lane;
                a0 = fmaf(g0, __ldg(yr),      a0);
                a1 = fmaf(g1, __ldg(yr + 32), a1);
                a2 = fmaf(g2, __ldg(yr + 64), a2);
            }
        }
        out[(size_t)n * 32 + lane] = a0 + a1 + a2;
    }
}

// ---- H = 16: two nodes per warp (half-warp each), 4 nodes staged ----------
template<int NWARP>
__global__ void __launch_bounds__(NWARP * 32)
gather_h16(const int* __restrict__ row_ptr, const int* __restrict__ col_idx,
           const float2* __restrict__ p,
           const float* __restrict__ mu, const float* __restrict__ sigma,
           const float* __restrict__ y,      // [N, 48]
           float* __restrict__ out,          // [N, 16]
           int n_nodes)
{
    constexpr int GRP = 4, CAP = 64;
    __shared__ float4 stg[NWARP][CAP];

    const int lane = threadIdx.x & 31;
    const int wid  = threadIdx.x >> 5;
    const int s    = lane >> 4;          // which node of the pair
    const int h    = lane & 15;
    const int base = (blockIdx.x * NWARP + wid) * GRP;
    if (base >= n_nodes) return;

    LOAD_GAUSS_PARAMS();

    const int ng   = min(GRP, n_nodes - base);
    const int e0   = row_ptr[base];
    const int ecnt = row_ptr[base + ng] - e0;
    const bool fast = (ecnt <= CAP);

    if (fast) {
        for (int j = lane; j < ecnt; j += 32) {
            const int e = e0 + j;
            const int c = col_idx[e];
            const float2 pv = __ldg(p + e);
            float g0, g1, g2; GAUSS3(pv, g0, g1, g2);
            stg[wid][j] = make_float4(g0, g1, g2, __int_as_float(c));
        }
    }
    __syncwarp();

    #pragma unroll
    for (int pi = 0; pi < 2; pi++) {
        const int n = base + pi * 2 + s;
        const bool valid = (n < n_nodes);
        const int nc  = valid ? n : base;
        const int st  = row_ptr[nc];
        const int deg = valid ? (row_ptr[nc + 1] - st) : 0;
        float a0 = 0.f, a1 = 0.f, a2 = 0.f;

        if (fast) {
            const float4* sd = &stg[wid][st - e0];
            const bool u16 = __all_sync(0xffffffffu, deg == 16);
            #define G16_BODY(J) do {                                          \
                const float4 ed = sd[(J)];                                    \
                const int c = __float_as_int(ed.w);                           \
                const float* yr = y + (size_t)c * 48 + h;                     \
                a0 = fmaf(ed.x, __ldg(yr),      a0);                          \
                a1 = fmaf(ed.y, __ldg(yr + 16), a1);                          \
                a2 = fmaf(ed.z, __ldg(yr + 32), a2);                          \
            } while (0)
            if (u16) {
                #pragma unroll
                for (int j = 0; j < 16; j++) G16_BODY(j);
            } else {
                for (int j = 0; j < deg; j++) G16_BODY(j);
            }
            #undef G16_BODY
        } else {
            const int maxd = __reduce_max_sync(0xffffffffu, deg);
            for (int j = 0; j < maxd; j++) {
                if (j < deg) {
                    const int e = st + j;
                    const int c = __ldg(col_idx + e);
                    const float2 pv = __ldg(p + e);
                    float g0, g1, g2; GAUSS3(pv, g0, g1, g2);
                    const float* yr = y + (size_t)c * 48 + h;
                    a0 = fmaf(g0, __ldg(yr),      a0);
                    a1 = fmaf(g1, __ldg(yr + 16), a1);
                    a2 = fmaf(g2, __ldg(yr + 32), a2);
                }
            }
        }
        if (valid) out[(size_t)n * 16 + h] = a0 + a1 + a2;
    }
}

// =============================== launch ====================================
extern "C" void kernel_launch(void* const* d_in, const int* in_sizes, int n_in,
                              void* d_out, int out_size)
{
    const int*    row_ptr = (const int*)d_in[0];    // int32 (JAX x64 disabled)
    const int*    col_idx = (const int*)d_in[1];
    const float*  x       = (const float*)d_in[2];
    const float2* p       = (const float2*)d_in[3];
    const float*  mu      = (const float*)d_in[4];
    const float*  sg      = (const float*)d_in[5];
    const float*  W1      = (const float*)d_in[6];
    const float*  W2      = (const float*)d_in[7];

    const int n_nodes = in_sizes[0] - 1;

    float *y1p, *hp, *y2p;
    cudaGetSymbolAddress((void**)&y1p, g_y1);
    cudaGetSymbolAddress((void**)&hp,  g_h);
    cudaGetSymbolAddress((void**)&y2p, g_y2);

    constexpr int NWARP = 8;
    const int gblocks = (n_nodes + NWARP * 4 - 1) / (NWARP * 4);
    const int tblocks = (n_nodes + 127) / 128;

    constexpr size_t smem_t1 = (64 * 130 + 64 * 96) * sizeof(float);  // 57.9KB
    constexpr size_t smem_t2 = (32 * 130 + 32 * 48) * sizeof(float);  // 22.8KB

    cudaFuncSetAttribute(transform_kernel<64, 96, 32>,
                         cudaFuncAttributeMaxDynamicSharedMemorySize, (int)smem_t1);
    cudaFuncSetAttribute(transform_kernel<32, 48, 16>,
                         cudaFuncAttributeMaxDynamicSharedMemorySize, (int)smem_t2);

    // T1: y1 = x * W1
    transform_kernel<64, 96, 32><<<tblocks, 192, smem_t1>>>(x, W1, y1p, n_nodes);
    // G1: h = gather(y1)
    gather_h32<NWARP><<<gblocks, NWARP * 32>>>(row_ptr, col_idx, p, mu, sg,
                                               y1p, hp, n_nodes);
    // T2: y2 = h * W2
    transform_kernel<32, 48, 16><<<tblocks, 192, smem_t2>>>(hp, W2, y2p, n_nodes);
    // G2: out = gather(y2)
    gather_h16<NWARP><<<gblocks, NWARP * 32>>>(row_ptr, col_idx, p, mu, sg,
                                               y2p, (float*)d_out, n_nodes);
}

// round 5
// speedup vs baseline: 1.5021x; 1.2401x over previous
#include <cuda_runtime.h>
#include <cuda_fp16.h>
#include <cstddef>

// ---------------------------------------------------------------------------
// GMM (MoNet) graph conv, transform-then-gather, fp16 intermediates:
//   T: y[m, k*H+h] = sum_f x[m,f] * W[k,f,h]      (ffma2 GEMM, half2 output)
//   G: out[n,h]    = sum_e sum_k gauss[e,k] * y[col_e, k*H+h]   (flat gather)
// T1(64->96 fp16), G1(H=32, f32 out), T2(32->48 fp16), G2(H=16, f32 out).
// ---------------------------------------------------------------------------

#define MAXN 131072
__device__ __half g_y1[MAXN * 96];   // xW1  [N,3,32]  fp16
__device__ float  g_h [MAXN * 32];   // layer1 out     f32
__device__ __half g_y2[MAXN * 48];   // hW2  [N,3,16]  fp16

typedef unsigned long long ull;

__device__ __forceinline__ ull pk2(float x, float y) {
    ull r; asm("mov.b64 %0, {%1,%2};" : "=l"(r) : "f"(x), "f"(y)); return r;
}
__device__ __forceinline__ void upk2(ull v, float& x, float& y) {
    asm("mov.b64 {%0,%1}, %2;" : "=f"(x), "=f"(y) : "l"(v));
}
__device__ __forceinline__ void ffma2(ull& d, ull a, ull b) {
    asm("fma.rn.f32x2 %0, %1, %2, %0;" : "+l"(d) : "l"(a), "l"(b));
}

// ======================= transform (tiled GEMM, half2 out) =================
// Y[m, j] (half2, j indexes h-pairs, NC2 = 3*H/2 pairs per row)
// blockDim 192 = 12 (j-dir) x 16 (m-dir); M-tile 128.
template<int KD, int H>
__global__ void __launch_bounds__(192)
transform_kernel(const float* __restrict__ X, const float* __restrict__ W,
                 __half2* __restrict__ Y, int n_nodes)
{
    constexpr int NCOL = 3 * H;
    constexpr int NC2  = NCOL / 2;         // 48 (T1) or 24 (T2)
    constexpr int NT   = NC2 / 12;         // 4 (T1) or 2 (T2)
    constexpr int MT   = 128;
    constexpr int XSTR = MT + 2;

    extern __shared__ float smem[];
    float* Xs = smem;                      // [KD][XSTR]
    float* Ws = smem + KD * XSTR;          // [KD][NCOL]

    const int tid = threadIdx.x;
    const int mt0 = blockIdx.x * MT;

    for (int i = tid; i < KD * NCOL; i += 192) {
        int f = i / NCOL, n = i % NCOL;
        int k = n / H, h = n % H;
        Ws[f * NCOL + n] = W[((size_t)k * KD + f) * H + h];
    }
    for (int i = tid; i < MT * KD; i += 192) {
        int m = i / KD, f = i % KD;
        float v = 0.f;
        if (mt0 + m < n_nodes) v = X[(size_t)(mt0 + m) * KD + f];
        Xs[f * XSTR + m] = v;
    }
    __syncthreads();

    const int tx = tid % 12;               // j-pair group
    const int ty = tid / 12;               // 0..15
    const int m0 = ty * 8;

    ull acc[8][NT];                        // [m][jpair] fp32 pair accumulators
    #pragma unroll
    for (int i = 0; i < 8; i++)
        #pragma unroll
        for (int s = 0; s < NT; s++) acc[i][s] = 0ull;

    for (int f = 0; f < KD; f++) {
        float xm[8];
        #pragma unroll
        for (int i = 0; i < 4; i++) {
            const ull xp = *(const ull*)&Xs[f * XSTR + m0 + 2 * i];
            upk2(xp, xm[2 * i], xm[2 * i + 1]);
        }
        #pragma unroll
        for (int s = 0; s < NT; s++) {
            const ull wp = *(const ull*)&Ws[f * NCOL + 2 * (tx + 12 * s)];
            #pragma unroll
            for (int i = 0; i < 8; i++)
                ffma2(acc[i][s], pk2(xm[i], xm[i]), wp);
        }
    }

    #pragma unroll
    for (int i = 0; i < 8; i++) {
        const int m = mt0 + m0 + i;
        if (m >= n_nodes) break;
        #pragma unroll
        for (int s = 0; s < NT; s++) {
            float v0, v1; upk2(acc[i][s], v0, v1);
            Y[(size_t)m * NC2 + tx + 12 * s] = __floats2half2_rn(v0, v1);
        }
    }
}

// ========================= gather kernels ==================================
#define LOAD_GAUSS_PARAMS()                                                   \
    const float m0_ = mu[0], m1_ = mu[1], m2_ = mu[2],                        \
                m3_ = mu[3], m4_ = mu[4], m5_ = mu[5];                        \
    float s_;                                                                 \
    s_ = sigma[0]; const float i0_ = 1.f/(s_*s_);                             \
    s_ = sigma[1]; const float i1_ = 1.f/(s_*s_);                             \
    s_ = sigma[2]; const float i2_ = 1.f/(s_*s_);                             \
    s_ = sigma[3]; const float i3_ = 1.f/(s_*s_);                             \
    s_ = sigma[4]; const float i4_ = 1.f/(s_*s_);                             \
    s_ = sigma[5]; const float i5_ = 1.f/(s_*s_);

#define GAUSS3(pv, g0, g1, g2) do {                                           \
    float dx_, dy_, q_;                                                       \
    dx_ = (pv).x - m0_; dy_ = (pv).y - m1_;                                   \
    q_ = dx_*dx_*i0_ + dy_*dy_*i1_; g0 = __expf(-0.5f * q_);                  \
    dx_ = (pv).x - m2_; dy_ = (pv).y - m3_;                                   \
    q_ = dx_*dx_*i2_ + dy_*dy_*i3_; g1 = __expf(-0.5f * q_);                  \
    dx_ = (pv).x - m4_; dy_ = (pv).y - m5_;                                   \
    q_ = dx_*dx_*i4_ + dy_*dy_*i5_; g2 = __expf(-0.5f * q_);                  \
} while (0)

// Generic gather: LPN lanes per node (16 for H=32, 8 for H=16), each lane
// owns an h-pair via one half2 load per k. y rows have RC2 = 3*H/2 half2.
template<int NWARP, int H, int LPN>
__global__ void __launch_bounds__(NWARP * 32)
gather_kernel(const int* __restrict__ row_ptr, const int* __restrict__ col_idx,
              const float2* __restrict__ p,
              const float* __restrict__ mu, const float* __restrict__ sigma,
              const __half2* __restrict__ y,   // [N, RC2] half2
              float* __restrict__ out,         // [N, H]  f32
              int n_nodes)
{
    constexpr int GRP = 4, CAP = GRP * 16;
    constexpr int H2  = H / 2;               // half2 per k-slice
    constexpr int RC2 = 3 * H2;              // row length in half2
    constexpr int NPN = 32 / LPN;            // nodes processed per warp pass

    __shared__ float4 stg[NWARP][CAP];

    const int lane = threadIdx.x & 31;
    const int wid  = threadIdx.x >> 5;
    const int s    = lane / LPN;             // node slot within pass
    const int hl   = lane % LPN;             // h-pair index
    const int base = (blockIdx.x * NWARP + wid) * GRP;
    if (base >= n_nodes) return;

    LOAD_GAUSS_PARAMS();

    const int ng   = min(GRP, n_nodes - base);
    const int e0   = row_ptr[base];
    const int ecnt = row_ptr[base + ng] - e0;
    const bool fast = (ecnt <= CAP);

    if (fast) {
        for (int j = lane; j < ecnt; j += 32) {
            const int e = e0 + j;
            const int c = col_idx[e];
            const float2 pv = __ldg(p + e);
            float g0, g1, g2; GAUSS3(pv, g0, g1, g2);
            stg[wid][j] = make_float4(g0, g1, g2, __int_as_float(c));
        }
    }
    __syncwarp();

    #pragma unroll
    for (int pi = 0; pi < GRP / NPN; pi++) {
        const int n = base + pi * NPN + s;
        const bool valid = (n < n_nodes);
        const int nc  = valid ? n : base;
        const int st  = __ldg(row_ptr + nc);
        const int deg = valid ? (__ldg(row_ptr + nc + 1) - st) : 0;

        ull a0 = 0ull, a1 = 0ull, a2 = 0ull;

        if (fast) {
            const float4* sd = &stg[wid][st - e0];
            const bool u16 = __all_sync(0xffffffffu, deg == 16);
            #define G_BODY(J) do {                                            \
                const float4 ed = sd[(J)];                                    \
                const int c = __float_as_int(ed.w);                           \
                const __half2* yr = y + (size_t)c * RC2 + hl;                 \
                const float2 f0 = __half22float2(__ldg(yr));                  \
                const float2 f1 = __half22float2(__ldg(yr + H2));             \
                const float2 f2 = __half22float2(__ldg(yr + 2 * H2));         \
                ffma2(a0, pk2(ed.x, ed.x), pk2(f0.x, f0.y));                  \
                ffma2(a1, pk2(ed.y, ed.y), pk2(f1.x, f1.y));                  \
                ffma2(a2, pk2(ed.z, ed.z), pk2(f2.x, f2.y));                  \
            } while (0)
            if (u16) {
                #pragma unroll
                for (int j = 0; j < 16; j++) G_BODY(j);
            } else {
                const int maxd = __reduce_max_sync(0xffffffffu, deg);
                for (int j = 0; j < maxd; j++)
                    if (j < deg) G_BODY(j);
            }
            #undef G_BODY
        } else {
            const int maxd = __reduce_max_sync(0xffffffffu, deg);
            for (int j = 0; j < maxd; j++) {
                if (j < deg) {
                    const int e = st + j;
                    const int c = __ldg(col_idx + e);
                    const float2 pv = __ldg(p + e);
                    float g0, g1, g2; GAUSS3(pv, g0, g1, g2);
                    const __half2* yr = y + (size_t)c * RC2 + hl;
                    const float2 f0 = __half22float2(__ldg(yr));
                    const float2 f1 = __half22float2(__ldg(yr + H2));
                    const float2 f2 = __half22float2(__ldg(yr + 2 * H2));
                    ffma2(a0, pk2(g0, g0), pk2(f0.x, f0.y));
                    ffma2(a1, pk2(g1, g1), pk2(f1.x, f1.y));
                    ffma2(a2, pk2(g2, g2), pk2(f2.x, f2.y));
                }
            }
        }

        if (valid) {
            float x0, x1, y0v, y1v, z0, z1;
            upk2(a0, x0, x1); upk2(a1, y0v, y1v); upk2(a2, z0, z1);
            float2 o = make_float2(x0 + y0v + z0, x1 + y1v + z1);
            *(float2*)(out + (size_t)n * H + 2 * hl) = o;
        }
    }
}

// =============================== launch ====================================
extern "C" void kernel_launch(void* const* d_in, const int* in_sizes, int n_in,
                              void* d_out, int out_size)
{
    const int*    row_ptr = (const int*)d_in[0];    // int32 (JAX x64 disabled)
    const int*    col_idx = (const int*)d_in[1];
    const float*  x       = (const float*)d_in[2];
    const float2* p       = (const float2*)d_in[3];
    const float*  mu      = (const float*)d_in[4];
    const float*  sg      = (const float*)d_in[5];
    const float*  W1      = (const float*)d_in[6];
    const float*  W2      = (const float*)d_in[7];

    const int n_nodes = in_sizes[0] - 1;

    __half2 *y1p, *y2p; float* hp;
    cudaGetSymbolAddress((void**)&y1p, g_y1);
    cudaGetSymbolAddress((void**)&hp,  g_h);
    cudaGetSymbolAddress((void**)&y2p, g_y2);

    constexpr int NWARP = 8;
    const int gblocks = (n_nodes + NWARP * 4 - 1) / (NWARP * 4);
    const int tblocks = (n_nodes + 127) / 128;

    constexpr size_t smem_t1 = (64 * 130 + 64 * 96) * sizeof(float);  // 57.9KB
    constexpr size_t smem_t2 = (32 * 130 + 32 * 48) * sizeof(float);  // 22.8KB

    cudaFuncSetAttribute(transform_kernel<64, 32>,
                         cudaFuncAttributeMaxDynamicSharedMemorySize, (int)smem_t1);
    cudaFuncSetAttribute(transform_kernel<32, 16>,
                         cudaFuncAttributeMaxDynamicSharedMemorySize, (int)smem_t2);

    // T1: y1 = x * W1  (fp16)
    transform_kernel<64, 32><<<tblocks, 192, smem_t1>>>(x, W1, y1p, n_nodes);
    // G1: h = gather(y1)  (H=32, 16 lanes/node)
    gather_kernel<NWARP, 32, 16><<<gblocks, NWARP * 32>>>(
        row_ptr, col_idx, p, mu, sg, y1p, hp, n_nodes);
    // T2: y2 = h * W2  (fp16)
    transform_kernel<32, 16><<<tblocks, 192, smem_t2>>>(hp, W2, y2p, n_nodes);
    // G2: out = gather(y2)  (H=16, 8 lanes/node)
    gather_kernel<NWARP, 16, 8><<<gblocks, NWARP * 32>>>(
        row_ptr, col_idx, p, mu, sg, y2p, (float*)d_out, n_nodes);
}